// round 12
// baseline (speedup 1.0000x reference)
#include <cuda_runtime.h>
#include <cuda_bf16.h>
#include <math.h>
#include <stdint.h>

#define Bv 64
#define Pv 80
#define LCv 18
#define Ev 256
#define Kw 3
#define WNv 16
#define LCHv 4
#define Hv 1024
#define Dv 260
#define TAGSv 50
#define ROWS (Bv*Pv)      /* 5120 */
#define G4 (4*Hv)         /* 4096 */

// persistent LSTM config
#define NB 128
#define NT 256
#define NLEAF 16
#define AW_STRIDE 516     /* words; row stride 1032 bf16 -> ldmatrix conflict-free */
#define WW_STRIDE 516
#define HS_STRIDE 1032    /* g_HSb padded row stride (bf16) == smem layout */
#define HROW_BYTES (HS_STRIDE*2)        /* 2064 */
#define HCHUNK_BYTES (16*HROW_BYTES)    /* 33024: 16 rows per TMA chunk */

// ingemm / tag tile strides
#define XS_STRIDE 268
#define TG_STRIDE 140

// ---- scratch ----
__device__ float g_X[ROWS*Dv];
__device__ float g_Gin[(size_t)ROWS*G4];
__device__ __align__(256) __nv_bfloat16 g_HSb[(size_t)ROWS*HS_STRIDE];
__device__ float g_TS[ROWS*TAGSv];
__device__ unsigned g_leaf[NLEAF*32];   /* 128B-separated leaf counters */
__device__ unsigned g_root[32];
__device__ unsigned g_gen[32];          /* single release flag (own line) */

// ---- helpers --------------------------------------------------------------
__device__ __forceinline__ uint32_t f2tf32(float f) {
    uint32_t r; asm("cvt.rna.tf32.f32 %0, %1;" : "=r"(r) : "f"(f)); return r;
}
__device__ __forceinline__ void mma_tf32(float* d, uint32_t a0, uint32_t a1,
                                         uint32_t a2, uint32_t a3,
                                         uint32_t b0, uint32_t b1) {
    asm volatile(
        "mma.sync.aligned.m16n8k8.row.col.f32.tf32.tf32.f32 "
        "{%0,%1,%2,%3}, {%4,%5,%6,%7}, {%8,%9}, {%0,%1,%2,%3};\n"
        : "+f"(d[0]), "+f"(d[1]), "+f"(d[2]), "+f"(d[3])
        : "r"(a0), "r"(a1), "r"(a2), "r"(a3), "r"(b0), "r"(b1));
}
__device__ __forceinline__ void mma_bf16(float* d, uint32_t a0, uint32_t a1,
                                         uint32_t a2, uint32_t a3,
                                         uint32_t b0, uint32_t b1) {
    asm volatile(
        "mma.sync.aligned.m16n8k16.row.col.f32.bf16.bf16.f32 "
        "{%0,%1,%2,%3}, {%4,%5,%6,%7}, {%8,%9}, {%0,%1,%2,%3};\n"
        : "+f"(d[0]), "+f"(d[1]), "+f"(d[2]), "+f"(d[3])
        : "r"(a0), "r"(a1), "r"(a2), "r"(a3), "r"(b0), "r"(b1));
}
__device__ __forceinline__ void cp16(void* sdst, const void* gsrc) {
    uint32_t s = (uint32_t)__cvta_generic_to_shared(sdst);
    asm volatile("cp.async.cg.shared.global [%0], [%1], 16;\n" :: "r"(s), "l"(gsrc));
}
__device__ __forceinline__ uint32_t sm32(const void* p) {
    return (uint32_t)__cvta_generic_to_shared(p);
}
__device__ __forceinline__ void ldsm_x4(uint32_t& r0, uint32_t& r1,
                                        uint32_t& r2, uint32_t& r3, uint32_t addr) {
    asm volatile("ldmatrix.sync.aligned.m8n8.x4.shared.b16 {%0,%1,%2,%3}, [%4];"
        : "=r"(r0), "=r"(r1), "=r"(r2), "=r"(r3) : "r"(addr));
}
__device__ __forceinline__ void mbar_init(uint32_t a, uint32_t cnt) {
    asm volatile("mbarrier.init.shared.b64 [%0], %1;" :: "r"(a), "r"(cnt) : "memory");
}
__device__ __forceinline__ void mbar_expect(uint32_t a, uint32_t bytes) {
    asm volatile("mbarrier.arrive.expect_tx.shared.b64 _, [%0], %1;"
                 :: "r"(a), "r"(bytes) : "memory");
}
__device__ __forceinline__ void bulk_ld_mc(uint32_t sdst, const void* g,
                                           uint32_t bytes, uint32_t mbar,
                                           uint16_t mask) {
    asm volatile(
        "cp.async.bulk.shared::cluster.global.mbarrier::complete_tx::bytes"
        ".multicast::cluster [%0], [%1], %2, [%3], %4;"
        :: "r"(sdst), "l"(g), "r"(bytes), "r"(mbar), "h"(mask) : "memory");
}
__device__ __forceinline__ void mbar_wait(uint32_t a, uint32_t parity) {
    uint32_t done;
    asm volatile(
        "{\n.reg .pred p;\n"
        "mbarrier.try_wait.parity.acquire.cta.shared::cta.b64 p, [%1], %2;\n"
        "selp.b32 %0, 1, 0, p;\n}"
        : "=r"(done) : "r"(a), "r"(parity) : "memory");
    while (!done) {
        asm volatile(
            "{\n.reg .pred p;\n"
            "mbarrier.try_wait.parity.acquire.cta.shared::cta.b64 p, [%1], %2, 0x989680;\n"
            "selp.b32 %0, 1, 0, p;\n}"
            : "=r"(done) : "r"(a), "r"(parity) : "memory");
    }
}
__device__ __forceinline__ unsigned atom_acqrel(unsigned* p, unsigned v) {
    unsigned r;
    asm volatile("atom.add.acq_rel.gpu.global.u32 %0, [%1], %2;"
                 : "=r"(r) : "l"(p), "r"(v) : "memory");
    return r;
}
__device__ __forceinline__ void st_release(unsigned* p, unsigned v) {
    asm volatile("st.release.gpu.global.u32 [%0], %1;" :: "l"(p), "r"(v) : "memory");
}
__device__ __forceinline__ unsigned ld_acquire(const unsigned* p) {
    unsigned r;
    asm volatile("ld.acquire.gpu.global.u32 %0, [%1];" : "=r"(r) : "l"(p) : "memory");
    return r;
}
__device__ __forceinline__ float fsig(float x) {
    return __fdividef(1.f, 1.f + __expf(-x));
}
__device__ __forceinline__ float ftanh(float x) {
    return __fdividef(2.f, 1.f + __expf(-2.f*x)) - 1.f;
}

// ---------------------------------------------------------------------------
__global__ void k_init() {
    int i = threadIdx.x;
    if (i < NLEAF*32) g_leaf[i] = 0u;
    if (i < 32) { g_root[i] = 0u; g_gen[i] = 0u; }
}

// ---- embedding + char CNN -------------------------------------------------
__global__ void k_embed(const int* __restrict__ sent, const int* __restrict__ chars,
                        const float* __restrict__ wemb, const float* __restrict__ cemb,
                        const float* __restrict__ convw, const float* __restrict__ convb) {
    __shared__ float ce[LCv*Ev];
    __shared__ float phi[WNv*LCHv];
    int bp = blockIdx.x;
    int tid = threadIdx.x;

    for (int u = tid; u < LCv*Ev; u += 128) {
        int l = u >> 8, e = u & 255;
        int ci = chars[bp*LCv + l];
        ce[u] = cemb[(size_t)ci*Ev + e];
    }
    __syncthreads();

    int wi = sent[bp];
    for (int e = tid; e < Ev; e += 128)
        g_X[(size_t)bp*Dv + e] = wemb[(size_t)wi*Ev + e];

    if (tid < WNv*LCHv) {
        int w = tid >> 2, c = tid & 3;
        float s = convb[c];
        #pragma unroll
        for (int k = 0; k < Kw; k++) {
            const float* cw = convw + c*(Kw*Ev) + k*Ev;
            const float* cc = ce + (w + k)*Ev;
            for (int e = 0; e < Ev; e++) s += cc[e]*cw[e];
        }
        phi[w*LCHv + c] = s;
    }
    __syncthreads();
    if (tid < LCHv) {
        float m = -1e30f;
        for (int w = 0; w < WNv; w++) m = fmaxf(m, phi[w*LCHv + tid]);
        g_X[(size_t)bp*Dv + Ev + tid] = m;
    }
}

// ---- input GEMM (tf32 MMA, 256 threads, W-tile reuse + double buffer) -----
__global__ void __launch_bounds__(256, 1) k_ingemm(const float* __restrict__ w_ih,
                                                   const float* __restrict__ b_ih,
                                                   const float* __restrict__ b_hh) {
    extern __shared__ uint32_t s[];
    uint32_t* Ws = s;
    uint32_t* Xb[2] = { s + 64*XS_STRIDE, s + 2*64*XS_STRIDE };
    const int j0 = blockIdx.x * 64;
    const int tid = threadIdx.x, warp = tid >> 5, lane = tid & 31;
    const int gid = lane >> 2, tig = lane & 3;
    const int m0 = (warp & 3) * 16, n0 = (warp >> 2) * 32;

    for (int r = tid; r < 64; r += 256) {
        #pragma unroll
        for (int c = 260; c < 268; c++) {
            Ws[r*XS_STRIDE + c] = 0u;
            Xb[0][r*XS_STRIDE + c] = 0u;
            Xb[1][r*XS_STRIDE + c] = 0u;
        }
    }
    for (int u = tid; u < 64*65; u += 256) {
        int r = u / 65, c = u - r*65;
        cp16(&Ws[r*XS_STRIDE + c*4], &w_ih[(size_t)(j0 + r)*Dv + c*4]);
    }
    {
        int i0 = (blockIdx.y*5 + 0) * 64;
        for (int u = tid; u < 64*65; u += 256) {
            int r = u / 65, c = u - r*65;
            cp16(&Xb[0][r*XS_STRIDE + c*4], &g_X[(size_t)(i0 + r)*Dv + c*4]);
        }
    }
    asm volatile("cp.async.commit_group;\n");

    for (int rt = 0; rt < 5; rt++) {
        const int i0 = (blockIdx.y*5 + rt) * 64;
        uint32_t* Xs = Xb[rt & 1];
        asm volatile("cp.async.wait_group 0;\n");
        __syncthreads();
        if (rt < 4) {
            int i1 = (blockIdx.y*5 + rt + 1) * 64;
            uint32_t* Xn = Xb[(rt+1) & 1];
            for (int u = tid; u < 64*65; u += 256) {
                int r = u / 65, c = u - r*65;
                cp16(&Xn[r*XS_STRIDE + c*4], &g_X[(size_t)(i1 + r)*Dv + c*4]);
            }
            asm volatile("cp.async.commit_group;\n");
        }

        float d[4][4] = {};
        #pragma unroll 1
        for (int kc = 0; kc < 33; kc++) {
            int kb = kc*8;
            int ar = (m0 + gid)*XS_STRIDE + kb;
            uint32_t a0 = Xs[ar + tig];
            uint32_t a1 = Xs[ar + 8*XS_STRIDE + tig];
            uint32_t a2 = Xs[ar + tig + 4];
            uint32_t a3 = Xs[ar + 8*XS_STRIDE + tig + 4];
            #pragma unroll
            for (int ns = 0; ns < 4; ns++) {
                uint32_t b0 = Ws[(n0 + ns*8 + gid)*XS_STRIDE + kb + tig];
                uint32_t b1 = Ws[(n0 + ns*8 + gid)*XS_STRIDE + kb + tig + 4];
                mma_tf32(d[ns], a0, a1, a2, a3, b0, b1);
            }
        }

        #pragma unroll
        for (int ns = 0; ns < 4; ns++) {
            int row = i0 + m0 + gid;
            int col = j0 + n0 + ns*8 + tig*2;
            float bb0 = b_ih[col] + b_hh[col];
            float bb1 = b_ih[col+1] + b_hh[col+1];
            *(float2*)&g_Gin[(size_t)row*G4 + col] =
                make_float2(d[ns][0] + bb0, d[ns][1] + bb1);
            *(float2*)&g_Gin[(size_t)(row+8)*G4 + col] =
                make_float2(d[ns][2] + bb0, d[ns][3] + bb1);
        }
        __syncthreads();
    }
}

// ---- persistent tensor-core LSTM ------------------------------------------
// tree arrive (16 leaves x 8) -> root -> single st.release flag; broadcast poll
__global__ void __launch_bounds__(NT, 1) __cluster_dims__(2, 1, 1)
k_lstm(const float* __restrict__ w_hh) {
    extern __shared__ uint32_t smw[];
    uint32_t* Aw  = smw;                               // h_prev bf16 [64][1032]
    uint32_t* Ww  = smw + 64*AW_STRIDE;                // W bf16 [32][1032]
    float*    Red = (float*)(smw + 64*AW_STRIDE + 32*WW_STRIDE); // [4][32][9]
    uint32_t  mbarBase = sm32(Red + 4*32*9);           // 4 mbarriers (8B each)

    const int tid  = threadIdx.x;
    const int warp = tid >> 5, lane = tid & 31;
    const int gid  = lane >> 2, tig = lane & 3;
    const int bx   = blockIdx.x;
    const int j0   = bx * 8;
    const int mt   = warp & 3, m0 = mt*16;
    const int nh   = warp >> 2;
    const int leaf = bx & (NLEAF-1);
    const uint32_t aw32 = sm32(Aw);
    uint32_t rank; asm("mov.u32 %0, %%cluster_ctarank;" : "=r"(rank));

    if (tid == 0) {
        #pragma unroll
        for (int c = 0; c < 4; c++) mbar_init(mbarBase + c*8, 1u);
    }

    // load + convert W slice to bf16 once
    {
        __nv_bfloat16* Whh = (__nv_bfloat16*)Ww;
        for (int u = tid; u < 32*Hv; u += NT) {
            int n = u >> 10, k = u & (Hv-1);
            int gate = n >> 3, jj = n & 7;
            Whh[n*(2*WW_STRIDE) + k] =
                __float2bfloat16(w_hh[(size_t)(gate*Hv + j0 + jj)*Hv + k]);
        }
    }
    __syncthreads();

    // per-lane ldmatrix base addresses
    const int sel = lane >> 3, lr = lane & 7;
    const int rowA  = m0 + lr + ((sel & 1) ? 8 : 0);
    const int wordA = (sel >= 2) ? 4 : 0;
    const uint32_t aBase = sm32(Aw + rowA*AW_STRIDE + wordA);
    const int rowW  = (nh*2 + (sel >> 1))*8 + lr;
    const int wordW = (sel & 1) ? 4 : 0;
    const uint32_t wBase = sm32(Ww + rowW*WW_STRIDE + wordW);

    float creg[4] = {0.f, 0.f, 0.f, 0.f};

    float2 gin[4];
    #pragma unroll
    for (int g2 = 0; g2 < 2; g2++)
        #pragma unroll
        for (int r = 0; r < 2; r++)
            gin[g2*2+r] = *(const float2*)
                &g_Gin[(size_t)(m0 + gid + r*8)*G4 + (nh*2+g2)*Hv + j0 + tig*2];

    for (int t = 0; t < Pv; t++) {
        float d[8], e[8];
        #pragma unroll
        for (int i = 0; i < 8; i++) { d[i] = 0.f; e[i] = 0.f; }

        if (t > 0) {
            // warp mt waits for its own 16-row chunk (issued in barrier path)
            mbar_wait(mbarBase + mt*8, (uint32_t)((t-1) & 1));

            #pragma unroll 2
            for (int kc = 0; kc < 64; kc += 2) {
                uint32_t a0, a1, a2, a3, w0, w1, w2, w3;
                uint32_t p0, p1, p2, p3, q0, q1, q2, q3;
                ldsm_x4(a0, a1, a2, a3, aBase + kc*32);
                ldsm_x4(w0, w1, w2, w3, wBase + kc*32);
                ldsm_x4(p0, p1, p2, p3, aBase + (kc+1)*32);
                ldsm_x4(q0, q1, q2, q3, wBase + (kc+1)*32);
                mma_bf16(d + 0, a0, a1, a2, a3, w0, w1);
                mma_bf16(d + 4, a0, a1, a2, a3, w2, w3);
                mma_bf16(e + 0, p0, p1, p2, p3, q0, q1);
                mma_bf16(e + 4, p0, p1, p2, p3, q2, q3);
            }
            #pragma unroll
            for (int i = 0; i < 8; i++) d[i] += e[i];
        }

        if (nh == 0) {
            float* rw = Red + (mt*32 + lane)*9;
            rw[0] = d[0] + gin[0].x; rw[1] = d[1] + gin[0].y;
            rw[2] = d[2] + gin[1].x; rw[3] = d[3] + gin[1].y;
            rw[4] = d[4] + gin[2].x; rw[5] = d[5] + gin[2].y;
            rw[6] = d[6] + gin[3].x; rw[7] = d[7] + gin[3].y;
        }
        // pairwise sync: warp mt (nh0) with warp mt+4 (nh1), 64 threads
        asm volatile("bar.sync %0, 64;" :: "r"(1 + mt) : "memory");

        if (nh == 1) {
            const float* rr = Red + (mt*32 + lane)*9;
            __nv_bfloat16* hdst = g_HSb + (size_t)t*Bv*HS_STRIDE;
            float hv[4];
            #pragma unroll
            for (int idx = 0; idx < 4; idx++) {
                int r = idx >> 1, p = idx & 1;
                float iv = rr[idx];
                float fv = rr[4 + idx];
                float gv = d[idx]     + ((p==0) ? gin[r].x   : gin[r].y);
                float ov = d[4 + idx] + ((p==0) ? gin[2+r].x : gin[2+r].y);
                float is = fsig(iv);
                float fs = fsig(fv);
                float gs = ftanh(gv);
                float os = fsig(ov);
                float cc = fs*creg[idx] + is*gs;
                creg[idx] = cc;
                hv[idx] = os*ftanh(cc);
            }
            __nv_bfloat162 h01, h23;
            h01.x = __float2bfloat16(hv[0]); h01.y = __float2bfloat16(hv[1]);
            h23.x = __float2bfloat16(hv[2]); h23.y = __float2bfloat16(hv[3]);
            *(__nv_bfloat162*)&hdst[(size_t)(m0 + gid)*HS_STRIDE + j0 + tig*2]     = h01;
            *(__nv_bfloat162*)&hdst[(size_t)(m0 + gid + 8)*HS_STRIDE + j0 + tig*2] = h23;
            // publish generic stores to the async proxy (peer TMA reads)
            asm volatile("fence.proxy.async;" ::: "memory");
        }

        // tree-arrive / flat-release grid barrier; TMA issue hoisted into exit
        if (t < Pv - 1) {
            __syncthreads();
            if (tid == 0) {
                unsigned lv = atom_acqrel(&g_leaf[leaf*32], 1u);
                if ((lv & 7u) == 7u) {               // last of 8 at this leaf
                    unsigned rv = atom_acqrel(&g_root[0], 1u);
                    if (rv == (unsigned)(NLEAF*t + NLEAF - 1))
                        st_release(&g_gen[0], (unsigned)(t + 1));
                }
            }
            // overlap: prefetch gin for t+1 while barrier settles
            #pragma unroll
            for (int g2 = 0; g2 < 2; g2++)
                #pragma unroll
                for (int r = 0; r < 2; r++)
                    gin[g2*2+r] = *(const float2*)
                        &g_Gin[(size_t)((t+1)*Bv + m0 + gid + r*8)*G4 + (nh*2+g2)*Hv + j0 + tig*2];
            if (tid == 0) {
                while (ld_acquire(&g_gen[0]) < (unsigned)(t + 1)) { }
                // issue h_t staging for step t+1: 2 chunks per CTA, multicast
                const char* src = (const char*)g_HSb
                    + (size_t)t * (size_t)(Bv*HROW_BYTES);
                #pragma unroll
                for (int c = 0; c < 4; c++)
                    mbar_expect(mbarBase + c*8, HCHUNK_BYTES);
                #pragma unroll
                for (int q = 0; q < 2; q++) {
                    int c = (int)rank*2 + q;
                    bulk_ld_mc(aw32 + c*HCHUNK_BYTES,
                               src + (size_t)c*HCHUNK_BYTES,
                               HCHUNK_BYTES, mbarBase + c*8, (uint16_t)3u);
                }
            }
            __syncthreads();
        }
    }

    // cluster-safe exit
    asm volatile("barrier.cluster.arrive.aligned;" ::: "memory");
    asm volatile("barrier.cluster.wait.aligned;" ::: "memory");
}

// ---- head GEMM (tf32 MMA; padded-HS reads) --------------------------------
__global__ void __launch_bounds__(128, 1) k_tag(const float* __restrict__ out_w,
                                                const float* __restrict__ out_b) {
    extern __shared__ uint32_t s[];
    uint32_t* As = s;                       // [64][140]
    uint32_t* Bs = s + 64*TG_STRIDE;        // [64][140]
    const int i0 = blockIdx.x * 64;
    const int tid = threadIdx.x, warp = tid >> 5, lane = tid & 31;
    const int gid = lane >> 2, tig = lane & 3;
    const int m0 = (warp & 1) * 32, n0 = (warp >> 1) * 32;

    float d[2][4][4] = {};
    for (int kc8 = 0; kc8 < 8; kc8++) {
        int kb = kc8 * 128;
        __syncthreads();
        for (int u = tid; u < 64*16; u += 128) {
            int r = u >> 4, c = u & 15;
            uint4 v = *(const uint4*)(g_HSb + (size_t)(i0 + r)*HS_STRIDE + kb + c*8);
            const uint32_t* pv = (const uint32_t*)&v;
            uint32_t* dst = &As[r*TG_STRIDE + c*8];
            #pragma unroll
            for (int j = 0; j < 4; j++) {
                dst[j*2]     = pv[j] << 16;
                dst[j*2 + 1] = pv[j] & 0xFFFF0000u;
            }
        }
        for (int u = tid; u < 64*32; u += 128) {
            int r = u >> 5, c = u & 31;
            float4 v = (r < TAGSv)
                ? *(const float4*)&out_w[(size_t)r*Hv + kb + c*4]
                : make_float4(0.f,0.f,0.f,0.f);
            uint4 tv = { f2tf32(v.x), f2tf32(v.y), f2tf32(v.z), f2tf32(v.w) };
            *(uint4*)&Bs[r*TG_STRIDE + c*4] = tv;
        }
        __syncthreads();

        #pragma unroll
        for (int kk = 0; kk < 16; kk++) {
            int kw = kk*8;
            uint32_t b[4][2];
            #pragma unroll
            for (int ns = 0; ns < 4; ns++) {
                b[ns][0] = Bs[(n0 + ns*8 + gid)*TG_STRIDE + kw + tig];
                b[ns][1] = Bs[(n0 + ns*8 + gid)*TG_STRIDE + kw + tig + 4];
            }
            #pragma unroll
            for (int ms = 0; ms < 2; ms++) {
                int ar = (m0 + ms*16 + gid)*TG_STRIDE + kw;
                uint32_t a0 = As[ar + tig];
                uint32_t a1 = As[ar + 8*TG_STRIDE + tig];
                uint32_t a2 = As[ar + tig + 4];
                uint32_t a3 = As[ar + 8*TG_STRIDE + tig + 4];
                #pragma unroll
                for (int ns = 0; ns < 4; ns++)
                    mma_tf32(d[ms][ns], a0, a1, a2, a3, b[ns][0], b[ns][1]);
            }
        }
    }

    #pragma unroll
    for (int ms = 0; ms < 2; ms++)
        #pragma unroll
        for (int ns = 0; ns < 4; ns++) {
            int row = i0 + m0 + ms*16 + gid;
            int col = n0 + ns*8 + tig*2;
            if (col < TAGSv) {
                float b0 = out_b[col];
                float b1 = (col+1 < TAGSv) ? out_b[col+1] : 0.f;
                g_TS[row*TAGSv + col] = d[ms][ns][0] + b0;
                if (col+1 < TAGSv) g_TS[row*TAGSv + col+1] = d[ms][ns][1] + b1;
                g_TS[(row+8)*TAGSv + col] = d[ms][ns][2] + b0;
                if (col+1 < TAGSv) g_TS[(row+8)*TAGSv + col+1] = d[ms][ns][3] + b1;
            }
        }
}

// ---- log_softmax over P (smem-staged, coalesced) --------------------------
__global__ void k_lsm(float* __restrict__ out) {
    __shared__ float ts[Pv*TAGSv];
    __shared__ float lse[TAGSv];
    int b = blockIdx.x;
    int tid = threadIdx.x;
    for (int u = tid; u < Pv*TAGSv; u += 256)
        ts[u] = g_TS[b*Pv*TAGSv + u];
    __syncthreads();
    if (tid < TAGSv) {
        float mx = -1e30f;
        for (int p = 0; p < Pv; p++) mx = fmaxf(mx, ts[p*TAGSv + tid]);
        float sacc = 0.f;
        for (int p = 0; p < Pv; p++) sacc += expf(ts[p*TAGSv + tid] - mx);
        lse[tid] = mx + logf(sacc);
    }
    __syncthreads();
    for (int u = tid; u < Pv*TAGSv; u += 256) {
        int tg = u - (u/TAGSv)*TAGSv;
        out[(size_t)b*Pv*TAGSv + u] = ts[u] - lse[tg];
    }
}

// ---------------------------------------------------------------------------
extern "C" void kernel_launch(void* const* d_in, const int* in_sizes, int n_in,
                              void* d_out, int out_size) {
    const int*   sent  = (const int*)  d_in[0];
    const int*   chars = (const int*)  d_in[1];
    const float* wemb  = (const float*)d_in[2];
    const float* cemb  = (const float*)d_in[3];
    const float* convw = (const float*)d_in[4];
    const float* convb = (const float*)d_in[5];
    const float* w_ih  = (const float*)d_in[6];
    const float* w_hh  = (const float*)d_in[7];
    const float* b_ih  = (const float*)d_in[8];
    const float* b_hh  = (const float*)d_in[9];
    const float* out_w = (const float*)d_in[10];
    const float* out_b = (const float*)d_in[11];
    float* out = (float*)d_out;

    const int SMEM_L  = (64*AW_STRIDE + 32*WW_STRIDE)*4 + 4*32*9*4 + 64;
    const int SMEM_IN = 3*64*XS_STRIDE*4;
    const int SMEM_TG = 2*64*TG_STRIDE*4;
    static int smem_set = 0;
    if (!smem_set) {
        cudaFuncSetAttribute(k_lstm,   cudaFuncAttributeMaxDynamicSharedMemorySize, SMEM_L);
        cudaFuncSetAttribute(k_ingemm, cudaFuncAttributeMaxDynamicSharedMemorySize, SMEM_IN);
        cudaFuncSetAttribute(k_tag,    cudaFuncAttributeMaxDynamicSharedMemorySize, SMEM_TG);
        smem_set = 1;
    }

    k_init<<<1, 512>>>();
    k_embed<<<ROWS, 128>>>(sent, chars, wemb, cemb, convw, convb);
    dim3 g2(G4/64, 16);
    k_ingemm<<<g2, 256, SMEM_IN>>>(w_ih, b_ih, b_hh);
    k_lstm<<<NB, NT, SMEM_L>>>(w_hh);
    k_tag<<<ROWS/64, 128, SMEM_TG>>>(out_w, out_b);
    k_lsm<<<Bv, 256>>>(out);
}

// round 16
// speedup vs baseline: 1.2292x; 1.2292x over previous
#include <cuda_runtime.h>
#include <cuda_bf16.h>
#include <math.h>
#include <stdint.h>

#define Bv 64
#define Pv 80
#define LCv 18
#define Ev 256
#define Kw 3
#define WNv 16
#define LCHv 4
#define Hv 1024
#define Dv 260
#define TAGSv 50
#define ROWS (Bv*Pv)      /* 5120 */
#define G4 (4*Hv)         /* 4096 */

// persistent LSTM config
#define NB 128
#define NT 256
#define AW_STRIDE 516     /* words; row stride 1032 bf16 -> ldmatrix conflict-free */
#define WW_STRIDE 516
#define HS_STRIDE 1032    /* g_HSb padded row stride (bf16) == smem layout */
#define HROW_BYTES (HS_STRIDE*2)        /* 2064 */
#define HCHUNK_BYTES (16*HROW_BYTES)    /* 33024: 16 rows per TMA chunk */

// ingemm / tag tile strides
#define XS_STRIDE 268
#define TG_STRIDE 140

// ---- scratch ----
__device__ float g_X[ROWS*Dv];
__device__ float g_Gin[(size_t)ROWS*G4];
__device__ __align__(256) __nv_bfloat16 g_HSb[(size_t)ROWS*HS_STRIDE];
__device__ float g_TS[ROWS*TAGSv];
__device__ unsigned g_cnt;
__device__ volatile unsigned g_gen;

// ---- helpers --------------------------------------------------------------
__device__ __forceinline__ uint32_t f2tf32(float f) {
    uint32_t r; asm("cvt.rna.tf32.f32 %0, %1;" : "=r"(r) : "f"(f)); return r;
}
__device__ __forceinline__ void mma_tf32(float* d, uint32_t a0, uint32_t a1,
                                         uint32_t a2, uint32_t a3,
                                         uint32_t b0, uint32_t b1) {
    asm volatile(
        "mma.sync.aligned.m16n8k8.row.col.f32.tf32.tf32.f32 "
        "{%0,%1,%2,%3}, {%4,%5,%6,%7}, {%8,%9}, {%0,%1,%2,%3};\n"
        : "+f"(d[0]), "+f"(d[1]), "+f"(d[2]), "+f"(d[3])
        : "r"(a0), "r"(a1), "r"(a2), "r"(a3), "r"(b0), "r"(b1));
}
__device__ __forceinline__ void mma_bf16(float* d, uint32_t a0, uint32_t a1,
                                         uint32_t a2, uint32_t a3,
                                         uint32_t b0, uint32_t b1) {
    asm volatile(
        "mma.sync.aligned.m16n8k16.row.col.f32.bf16.bf16.f32 "
        "{%0,%1,%2,%3}, {%4,%5,%6,%7}, {%8,%9}, {%0,%1,%2,%3};\n"
        : "+f"(d[0]), "+f"(d[1]), "+f"(d[2]), "+f"(d[3])
        : "r"(a0), "r"(a1), "r"(a2), "r"(a3), "r"(b0), "r"(b1));
}
__device__ __forceinline__ void cp16(void* sdst, const void* gsrc) {
    uint32_t s = (uint32_t)__cvta_generic_to_shared(sdst);
    asm volatile("cp.async.cg.shared.global [%0], [%1], 16;\n" :: "r"(s), "l"(gsrc));
}
__device__ __forceinline__ uint32_t sm32(const void* p) {
    return (uint32_t)__cvta_generic_to_shared(p);
}
__device__ __forceinline__ void ldsm_x4(uint32_t& r0, uint32_t& r1,
                                        uint32_t& r2, uint32_t& r3, uint32_t addr) {
    asm volatile("ldmatrix.sync.aligned.m8n8.x4.shared.b16 {%0,%1,%2,%3}, [%4];"
        : "=r"(r0), "=r"(r1), "=r"(r2), "=r"(r3) : "r"(addr));
}
__device__ __forceinline__ void mbar_init(uint32_t a, uint32_t cnt) {
    asm volatile("mbarrier.init.shared.b64 [%0], %1;" :: "r"(a), "r"(cnt) : "memory");
}
__device__ __forceinline__ void mbar_expect(uint32_t a, uint32_t bytes) {
    asm volatile("mbarrier.arrive.expect_tx.shared.b64 _, [%0], %1;"
                 :: "r"(a), "r"(bytes) : "memory");
}
__device__ __forceinline__ void bulk_ld_mc(uint32_t sdst, const void* g,
                                           uint32_t bytes, uint32_t mbar,
                                           uint16_t mask) {
    asm volatile(
        "cp.async.bulk.shared::cluster.global.mbarrier::complete_tx::bytes"
        ".multicast::cluster [%0], [%1], %2, [%3], %4;"
        :: "r"(sdst), "l"(g), "r"(bytes), "r"(mbar), "h"(mask) : "memory");
}
__device__ __forceinline__ void mbar_wait(uint32_t a, uint32_t parity) {
    uint32_t done;
    asm volatile(
        "{\n.reg .pred p;\n"
        "mbarrier.try_wait.parity.acquire.cta.shared::cta.b64 p, [%1], %2;\n"
        "selp.b32 %0, 1, 0, p;\n}"
        : "=r"(done) : "r"(a), "r"(parity) : "memory");
    while (!done) {
        asm volatile(
            "{\n.reg .pred p;\n"
            "mbarrier.try_wait.parity.acquire.cta.shared::cta.b64 p, [%1], %2, 0x989680;\n"
            "selp.b32 %0, 1, 0, p;\n}"
            : "=r"(done) : "r"(a), "r"(parity) : "memory");
    }
}
__device__ __forceinline__ float fsig(float x) {
    return __fdividef(1.f, 1.f + __expf(-x));
}
__device__ __forceinline__ float ftanh(float x) {
    return __fdividef(2.f, 1.f + __expf(-2.f*x)) - 1.f;
}

// ---- embedding + char CNN (vectorized; also resets barrier state) ---------
__global__ void k_embed(const int* __restrict__ sent, const int* __restrict__ chars,
                        const float* __restrict__ wemb, const float* __restrict__ cemb,
                        const float* __restrict__ convw, const float* __restrict__ convb) {
    __shared__ float4 ce4[LCv*65];     // char embs, padded rows (65 f4/char)
    __shared__ float4 cw4[LCHv*193];   // conv weights, padded rows
    __shared__ float  phi[WNv*LCHv];
    const int bp = blockIdx.x;
    const int tid = threadIdx.x;

    if (bp == 0 && tid == 0) { g_cnt = 0u; g_gen = 0u; }  // folded k_init

    // stage char embeddings (float4)
    for (int u = tid; u < LCv*64; u += 128) {
        int l = u >> 6, e4 = u & 63;
        int ci = chars[bp*LCv + l];
        ce4[l*65 + e4] = ((const float4*)cemb)[(size_t)ci*64 + e4];
    }
    // stage conv weights (float4, padded)
    for (int u = tid; u < LCHv*192; u += 128) {
        int c = u / 192, r = u - c*192;
        cw4[c*193 + r] = ((const float4*)convw)[(size_t)c*192 + r];
    }
    __syncthreads();

    // word embedding copy (float4; g_X row = bp*260 floats, 16B-aligned)
    int wi = sent[bp];
    for (int e4 = tid; e4 < 64; e4 += 128)
        *(float4*)&g_X[(size_t)bp*Dv + e4*4] = ((const float4*)wemb)[(size_t)wi*64 + e4];

    // conv: 16 windows x 4 channels; 4 accumulators, float4 smem reads
    if (tid < WNv*LCHv) {
        int w = tid >> 2, c = tid & 3;
        float s0 = 0.f, s1 = 0.f, s2 = 0.f, s3 = 0.f;
        #pragma unroll
        for (int k = 0; k < Kw; k++) {
            const float4* cc = ce4 + (w + k)*65;
            const float4* cw = cw4 + c*193 + k*64;
            #pragma unroll
            for (int e = 0; e < 64; e += 4) {
                float4 a0 = cc[e],   b0 = cw[e];
                float4 a1 = cc[e+1], b1 = cw[e+1];
                float4 a2 = cc[e+2], b2 = cw[e+2];
                float4 a3 = cc[e+3], b3 = cw[e+3];
                s0 += a0.x*b0.x + a0.y*b0.y + a0.z*b0.z + a0.w*b0.w;
                s1 += a1.x*b1.x + a1.y*b1.y + a1.z*b1.z + a1.w*b1.w;
                s2 += a2.x*b2.x + a2.y*b2.y + a2.z*b2.z + a2.w*b2.w;
                s3 += a3.x*b3.x + a3.y*b3.y + a3.z*b3.z + a3.w*b3.w;
            }
        }
        phi[w*LCHv + c] = s0 + s1 + s2 + s3 + convb[c];
    }
    __syncthreads();
    if (tid < LCHv) {
        float m = -1e30f;
        #pragma unroll
        for (int w = 0; w < WNv; w++) m = fmaxf(m, phi[w*LCHv + tid]);
        g_X[(size_t)bp*Dv + Ev + tid] = m;
    }
}

// ---- input GEMM (tf32 MMA, 256 threads, W-tile reuse + double buffer) -----
__global__ void __launch_bounds__(256, 1) k_ingemm(const float* __restrict__ w_ih,
                                                   const float* __restrict__ b_ih,
                                                   const float* __restrict__ b_hh) {
    extern __shared__ uint32_t s[];
    uint32_t* Ws = s;
    uint32_t* Xb[2] = { s + 64*XS_STRIDE, s + 2*64*XS_STRIDE };
    const int j0 = blockIdx.x * 64;
    const int tid = threadIdx.x, warp = tid >> 5, lane = tid & 31;
    const int gid = lane >> 2, tig = lane & 3;
    const int m0 = (warp & 3) * 16, n0 = (warp >> 2) * 32;

    for (int r = tid; r < 64; r += 256) {
        #pragma unroll
        for (int c = 260; c < 268; c++) {
            Ws[r*XS_STRIDE + c] = 0u;
            Xb[0][r*XS_STRIDE + c] = 0u;
            Xb[1][r*XS_STRIDE + c] = 0u;
        }
    }
    for (int u = tid; u < 64*65; u += 256) {
        int r = u / 65, c = u - r*65;
        cp16(&Ws[r*XS_STRIDE + c*4], &w_ih[(size_t)(j0 + r)*Dv + c*4]);
    }
    {
        int i0 = (blockIdx.y*5 + 0) * 64;
        for (int u = tid; u < 64*65; u += 256) {
            int r = u / 65, c = u - r*65;
            cp16(&Xb[0][r*XS_STRIDE + c*4], &g_X[(size_t)(i0 + r)*Dv + c*4]);
        }
    }
    asm volatile("cp.async.commit_group;\n");

    for (int rt = 0; rt < 5; rt++) {
        const int i0 = (blockIdx.y*5 + rt) * 64;
        uint32_t* Xs = Xb[rt & 1];
        asm volatile("cp.async.wait_group 0;\n");
        __syncthreads();
        if (rt < 4) {
            int i1 = (blockIdx.y*5 + rt + 1) * 64;
            uint32_t* Xn = Xb[(rt+1) & 1];
            for (int u = tid; u < 64*65; u += 256) {
                int r = u / 65, c = u - r*65;
                cp16(&Xn[r*XS_STRIDE + c*4], &g_X[(size_t)(i1 + r)*Dv + c*4]);
            }
            asm volatile("cp.async.commit_group;\n");
        }

        float d[4][4] = {};
        #pragma unroll 1
        for (int kc = 0; kc < 33; kc++) {
            int kb = kc*8;
            int ar = (m0 + gid)*XS_STRIDE + kb;
            uint32_t a0 = Xs[ar + tig];
            uint32_t a1 = Xs[ar + 8*XS_STRIDE + tig];
            uint32_t a2 = Xs[ar + tig + 4];
            uint32_t a3 = Xs[ar + 8*XS_STRIDE + tig + 4];
            #pragma unroll
            for (int ns = 0; ns < 4; ns++) {
                uint32_t b0 = Ws[(n0 + ns*8 + gid)*XS_STRIDE + kb + tig];
                uint32_t b1 = Ws[(n0 + ns*8 + gid)*XS_STRIDE + kb + tig + 4];
                mma_tf32(d[ns], a0, a1, a2, a3, b0, b1);
            }
        }

        #pragma unroll
        for (int ns = 0; ns < 4; ns++) {
            int row = i0 + m0 + gid;
            int col = j0 + n0 + ns*8 + tig*2;
            float bb0 = b_ih[col] + b_hh[col];
            float bb1 = b_ih[col+1] + b_hh[col+1];
            *(float2*)&g_Gin[(size_t)row*G4 + col] =
                make_float2(d[ns][0] + bb0, d[ns][1] + bb1);
            *(float2*)&g_Gin[(size_t)(row+8)*G4 + col] =
                make_float2(d[ns][2] + bb0, d[ns][3] + bb1);
        }
        __syncthreads();
    }
}

// ---- persistent tensor-core LSTM (R11 proven: flat barrier + TMA multicast)
__global__ void __launch_bounds__(NT, 1) __cluster_dims__(2, 1, 1)
k_lstm(const float* __restrict__ w_hh) {
    extern __shared__ uint32_t smw[];
    uint32_t* Aw  = smw;                               // h_prev bf16 [64][1032]
    uint32_t* Ww  = smw + 64*AW_STRIDE;                // W bf16 [32][1032]
    float*    Red = (float*)(smw + 64*AW_STRIDE + 32*WW_STRIDE); // [4][32][9]
    uint32_t  mbarBase = sm32(Red + 4*32*9);           // 4 mbarriers (8B each)

    const int tid  = threadIdx.x;
    const int warp = tid >> 5, lane = tid & 31;
    const int gid  = lane >> 2, tig = lane & 3;
    const int bx   = blockIdx.x;
    const int j0   = bx * 8;
    const int mt   = warp & 3, m0 = mt*16;
    const int nh   = warp >> 2;
    const uint32_t aw32 = sm32(Aw);
    uint32_t rank; asm("mov.u32 %0, %%cluster_ctarank;" : "=r"(rank));

    if (tid == 0) {
        #pragma unroll
        for (int c = 0; c < 4; c++) mbar_init(mbarBase + c*8, 1u);
    }

    // load + convert W slice to bf16 once
    {
        __nv_bfloat16* Whh = (__nv_bfloat16*)Ww;
        for (int u = tid; u < 32*Hv; u += NT) {
            int n = u >> 10, k = u & (Hv-1);
            int gate = n >> 3, jj = n & 7;
            Whh[n*(2*WW_STRIDE) + k] =
                __float2bfloat16(w_hh[(size_t)(gate*Hv + j0 + jj)*Hv + k]);
        }
    }
    __syncthreads();
    // peer mbar-init visibility: peer's first multicast TMA is issued only
    // after the global barrier of step 0.

    // per-lane ldmatrix base addresses
    const int sel = lane >> 3, lr = lane & 7;
    const int rowA  = m0 + lr + ((sel & 1) ? 8 : 0);
    const int wordA = (sel >= 2) ? 4 : 0;
    const uint32_t aBase = sm32(Aw + rowA*AW_STRIDE + wordA);
    const int rowW  = (nh*2 + (sel >> 1))*8 + lr;
    const int wordW = (sel & 1) ? 4 : 0;
    const uint32_t wBase = sm32(Ww + rowW*WW_STRIDE + wordW);

    float creg[4] = {0.f, 0.f, 0.f, 0.f};

    float2 gin[4];
    #pragma unroll
    for (int g2 = 0; g2 < 2; g2++)
        #pragma unroll
        for (int r = 0; r < 2; r++)
            gin[g2*2+r] = *(const float2*)
                &g_Gin[(size_t)(m0 + gid + r*8)*G4 + (nh*2+g2)*Hv + j0 + tig*2];

    for (int t = 0; t < Pv; t++) {
        float d[8];
        #pragma unroll
        for (int i = 0; i < 8; i++) d[i] = 0.f;

        if (t > 0) {
            // warp mt waits for its own 16-row chunk (issued in barrier path)
            mbar_wait(mbarBase + mt*8, (uint32_t)((t-1) & 1));

            #pragma unroll 4
            for (int kc = 0; kc < 64; kc++) {
                uint32_t a0, a1, a2, a3, w0, w1, w2, w3;
                ldsm_x4(a0, a1, a2, a3, aBase + kc*32);
                ldsm_x4(w0, w1, w2, w3, wBase + kc*32);
                mma_bf16(d + 0, a0, a1, a2, a3, w0, w1);
                mma_bf16(d + 4, a0, a1, a2, a3, w2, w3);
            }
        }

        if (nh == 0) {
            float* rw = Red + (mt*32 + lane)*9;
            rw[0] = d[0] + gin[0].x; rw[1] = d[1] + gin[0].y;
            rw[2] = d[2] + gin[1].x; rw[3] = d[3] + gin[1].y;
            rw[4] = d[4] + gin[2].x; rw[5] = d[5] + gin[2].y;
            rw[6] = d[6] + gin[3].x; rw[7] = d[7] + gin[3].y;
        }
        __syncthreads();

        if (nh == 1) {
            const float* rr = Red + (mt*32 + lane)*9;
            __nv_bfloat16* hdst = g_HSb + (size_t)t*Bv*HS_STRIDE;
            float hv[4];
            #pragma unroll
            for (int idx = 0; idx < 4; idx++) {
                int r = idx >> 1, p = idx & 1;
                float iv = rr[idx];
                float fv = rr[4 + idx];
                float gv = d[idx]     + ((p==0) ? gin[r].x   : gin[r].y);
                float ov = d[4 + idx] + ((p==0) ? gin[2+r].x : gin[2+r].y);
                float is = fsig(iv);
                float fs = fsig(fv);
                float gs = ftanh(gv);
                float os = fsig(ov);
                float cc = fs*creg[idx] + is*gs;
                creg[idx] = cc;
                hv[idx] = os*ftanh(cc);
            }
            __nv_bfloat162 h01, h23;
            h01.x = __float2bfloat16(hv[0]); h01.y = __float2bfloat16(hv[1]);
            h23.x = __float2bfloat16(hv[2]); h23.y = __float2bfloat16(hv[3]);
            *(__nv_bfloat162*)&hdst[(size_t)(m0 + gid)*HS_STRIDE + j0 + tig*2]     = h01;
            *(__nv_bfloat162*)&hdst[(size_t)(m0 + gid + 8)*HS_STRIDE + j0 + tig*2] = h23;
        }

        // flat grid barrier; TMA multicast issue for t+1 hoisted into exit path
        if (t < Pv - 1) {
            asm volatile("fence.proxy.async;" ::: "memory");
            __syncthreads();
            if (tid == 0) {
                __threadfence();
                unsigned a = atomicAdd(&g_cnt, 1u);
                if (a == NB - 1) {
                    g_cnt = 0u;
                    __threadfence();
                    atomicAdd((unsigned*)&g_gen, 1u);
                }
            }
            // overlap: prefetch gin for t+1 while barrier settles
            #pragma unroll
            for (int g2 = 0; g2 < 2; g2++)
                #pragma unroll
                for (int r = 0; r < 2; r++)
                    gin[g2*2+r] = *(const float2*)
                        &g_Gin[(size_t)((t+1)*Bv + m0 + gid + r*8)*G4 + (nh*2+g2)*Hv + j0 + tig*2];
            if (tid == 0) {
                while (g_gen < (unsigned)(t + 1)) { }
                __threadfence();
                // issue h_t staging for step t+1: 2 chunks per CTA, multicast
                const char* src = (const char*)g_HSb
                    + (size_t)t * (size_t)(Bv*HROW_BYTES);
                #pragma unroll
                for (int c = 0; c < 4; c++)
                    mbar_expect(mbarBase + c*8, HCHUNK_BYTES);
                #pragma unroll
                for (int q = 0; q < 2; q++) {
                    int c = (int)rank*2 + q;
                    bulk_ld_mc(aw32 + c*HCHUNK_BYTES,
                               src + (size_t)c*HCHUNK_BYTES,
                               HCHUNK_BYTES, mbarBase + c*8, (uint16_t)3u);
                }
            }
            __syncthreads();
        }
    }

    // cluster-safe exit
    asm volatile("barrier.cluster.arrive.aligned;" ::: "memory");
    asm volatile("barrier.cluster.wait.aligned;" ::: "memory");
}

// ---- head GEMM (tf32 MMA; padded-HS reads) --------------------------------
__global__ void __launch_bounds__(128, 1) k_tag(const float* __restrict__ out_w,
                                                const float* __restrict__ out_b) {
    extern __shared__ uint32_t s[];
    uint32_t* As = s;                       // [64][140]
    uint32_t* Bs = s + 64*TG_STRIDE;        // [64][140]
    const int i0 = blockIdx.x * 64;
    const int tid = threadIdx.x, warp = tid >> 5, lane = tid & 31;
    const int gid = lane >> 2, tig = lane & 3;
    const int m0 = (warp & 1) * 32, n0 = (warp >> 1) * 32;

    float d[2][4][4] = {};
    for (int kc8 = 0; kc8 < 8; kc8++) {
        int kb = kc8 * 128;
        __syncthreads();
        for (int u = tid; u < 64*16; u += 128) {
            int r = u >> 4, c = u & 15;
            uint4 v = *(const uint4*)(g_HSb + (size_t)(i0 + r)*HS_STRIDE + kb + c*8);
            const uint32_t* pv = (const uint32_t*)&v;
            uint32_t* dst = &As[r*TG_STRIDE + c*8];
            #pragma unroll
            for (int j = 0; j < 4; j++) {
                dst[j*2]     = pv[j] << 16;
                dst[j*2 + 1] = pv[j] & 0xFFFF0000u;
            }
        }
        for (int u = tid; u < 64*32; u += 128) {
            int r = u >> 5, c = u & 31;
            float4 v = (r < TAGSv)
                ? *(const float4*)&out_w[(size_t)r*Hv + kb + c*4]
                : make_float4(0.f,0.f,0.f,0.f);
            uint4 tv = { f2tf32(v.x), f2tf32(v.y), f2tf32(v.z), f2tf32(v.w) };
            *(uint4*)&Bs[r*TG_STRIDE + c*4] = tv;
        }
        __syncthreads();

        #pragma unroll
        for (int kk = 0; kk < 16; kk++) {
            int kw = kk*8;
            uint32_t b[4][2];
            #pragma unroll
            for (int ns = 0; ns < 4; ns++) {
                b[ns][0] = Bs[(n0 + ns*8 + gid)*TG_STRIDE + kw + tig];
                b[ns][1] = Bs[(n0 + ns*8 + gid)*TG_STRIDE + kw + tig + 4];
            }
            #pragma unroll
            for (int ms = 0; ms < 2; ms++) {
                int ar = (m0 + ms*16 + gid)*TG_STRIDE + kw;
                uint32_t a0 = As[ar + tig];
                uint32_t a1 = As[ar + 8*TG_STRIDE + tig];
                uint32_t a2 = As[ar + tig + 4];
                uint32_t a3 = As[ar + 8*TG_STRIDE + tig + 4];
                #pragma unroll
                for (int ns = 0; ns < 4; ns++)
                    mma_tf32(d[ms][ns], a0, a1, a2, a3, b[ns][0], b[ns][1]);
            }
        }
    }

    #pragma unroll
    for (int ms = 0; ms < 2; ms++)
        #pragma unroll
        for (int ns = 0; ns < 4; ns++) {
            int row = i0 + m0 + ms*16 + gid;
            int col = n0 + ns*8 + tig*2;
            if (col < TAGSv) {
                float b0 = out_b[col];
                float b1 = (col+1 < TAGSv) ? out_b[col+1] : 0.f;
                g_TS[row*TAGSv + col] = d[ms][ns][0] + b0;
                if (col+1 < TAGSv) g_TS[row*TAGSv + col+1] = d[ms][ns][1] + b1;
                g_TS[(row+8)*TAGSv + col] = d[ms][ns][2] + b0;
                if (col+1 < TAGSv) g_TS[(row+8)*TAGSv + col+1] = d[ms][ns][3] + b1;
            }
        }
}

// ---- log_softmax over P (smem-staged, coalesced) --------------------------
__global__ void k_lsm(float* __restrict__ out) {
    __shared__ float ts[Pv*TAGSv];
    __shared__ float lse[TAGSv];
    int b = blockIdx.x;
    int tid = threadIdx.x;
    for (int u = tid; u < Pv*TAGSv; u += 256)
        ts[u] = g_TS[b*Pv*TAGSv + u];
    __syncthreads();
    if (tid < TAGSv) {
        float mx = -1e30f;
        for (int p = 0; p < Pv; p++) mx = fmaxf(mx, ts[p*TAGSv + tid]);
        float sacc = 0.f;
        for (int p = 0; p < Pv; p++) sacc += expf(ts[p*TAGSv + tid] - mx);
        lse[tid] = mx + logf(sacc);
    }
    __syncthreads();
    for (int u = tid; u < Pv*TAGSv; u += 256) {
        int tg = u - (u/TAGSv)*TAGSv;
        out[(size_t)b*Pv*TAGSv + u] = ts[u] - lse[tg];
    }
}

// ---------------------------------------------------------------------------
extern "C" void kernel_launch(void* const* d_in, const int* in_sizes, int n_in,
                              void* d_out, int out_size) {
    const int*   sent  = (const int*)  d_in[0];
    const int*   chars = (const int*)  d_in[1];
    const float* wemb  = (const float*)d_in[2];
    const float* cemb  = (const float*)d_in[3];
    const float* convw = (const float*)d_in[4];
    const float* convb = (const float*)d_in[5];
    const float* w_ih  = (const float*)d_in[6];
    const float* w_hh  = (const float*)d_in[7];
    const float* b_ih  = (const float*)d_in[8];
    const float* b_hh  = (const float*)d_in[9];
    const float* out_w = (const float*)d_in[10];
    const float* out_b = (const float*)d_in[11];
    float* out = (float*)d_out;

    const int SMEM_L  = (64*AW_STRIDE + 32*WW_STRIDE)*4 + 4*32*9*4 + 64;
    const int SMEM_IN = 3*64*XS_STRIDE*4;
    const int SMEM_TG = 2*64*TG_STRIDE*4;
    static int smem_set = 0;
    if (!smem_set) {
        cudaFuncSetAttribute(k_lstm,   cudaFuncAttributeMaxDynamicSharedMemorySize, SMEM_L);
        cudaFuncSetAttribute(k_ingemm, cudaFuncAttributeMaxDynamicSharedMemorySize, SMEM_IN);
        cudaFuncSetAttribute(k_tag,    cudaFuncAttributeMaxDynamicSharedMemorySize, SMEM_TG);
        smem_set = 1;
    }

    k_embed<<<ROWS, 128>>>(sent, chars, wemb, cemb, convw, convb);
    dim3 g2(G4/64, 16);
    k_ingemm<<<g2, 256, SMEM_IN>>>(w_ih, b_ih, b_hh);
    k_lstm<<<NB, NT, SMEM_L>>>(w_hh);
    k_tag<<<ROWS/64, 128, SMEM_TG>>>(out_w, out_b);
    k_lsm<<<Bv, 256>>>(out);
}

// round 17
// speedup vs baseline: 1.4195x; 1.1548x over previous
#include <cuda_runtime.h>
#include <cuda_bf16.h>
#include <math.h>
#include <stdint.h>

#define Bv 64
#define Pv 80
#define LCv 18
#define Ev 256
#define Kw 3
#define WNv 16
#define LCHv 4
#define Hv 1024
#define Dv 260
#define TAGSv 50
#define ROWS (Bv*Pv)      /* 5120 */
#define G4 (4*Hv)         /* 4096 */

// persistent LSTM config
#define NB 128
#define NT 256
#define AW_STRIDE 516     /* words; row stride 1032 bf16 -> ldmatrix conflict-free */
#define WW_STRIDE 516
#define HS_STRIDE 1032    /* g_HSb padded row stride (bf16) == smem layout */
#define HROW_BYTES (HS_STRIDE*2)        /* 2064 */
#define HCHUNK_BYTES (16*HROW_BYTES)    /* 33024: 16 rows per TMA chunk */

// ingemm / tag tile strides
#define XS_STRIDE 268
#define TG_STRIDE 140

// ---- scratch ----
__device__ float g_X[ROWS*Dv];
__device__ float g_Gin[(size_t)ROWS*G4];
__device__ __align__(256) __nv_bfloat16 g_HSb[(size_t)ROWS*HS_STRIDE];
__device__ float g_TS[ROWS*TAGSv];
__device__ unsigned g_chk[4*32];   /* 4 monotonic chunk counters, 128B apart */

// ---- helpers --------------------------------------------------------------
__device__ __forceinline__ uint32_t f2tf32(float f) {
    uint32_t r; asm("cvt.rna.tf32.f32 %0, %1;" : "=r"(r) : "f"(f)); return r;
}
__device__ __forceinline__ void mma_tf32(float* d, uint32_t a0, uint32_t a1,
                                         uint32_t a2, uint32_t a3,
                                         uint32_t b0, uint32_t b1) {
    asm volatile(
        "mma.sync.aligned.m16n8k8.row.col.f32.tf32.tf32.f32 "
        "{%0,%1,%2,%3}, {%4,%5,%6,%7}, {%8,%9}, {%0,%1,%2,%3};\n"
        : "+f"(d[0]), "+f"(d[1]), "+f"(d[2]), "+f"(d[3])
        : "r"(a0), "r"(a1), "r"(a2), "r"(a3), "r"(b0), "r"(b1));
}
__device__ __forceinline__ void mma_bf16(float* d, uint32_t a0, uint32_t a1,
                                         uint32_t a2, uint32_t a3,
                                         uint32_t b0, uint32_t b1) {
    asm volatile(
        "mma.sync.aligned.m16n8k16.row.col.f32.bf16.bf16.f32 "
        "{%0,%1,%2,%3}, {%4,%5,%6,%7}, {%8,%9}, {%0,%1,%2,%3};\n"
        : "+f"(d[0]), "+f"(d[1]), "+f"(d[2]), "+f"(d[3])
        : "r"(a0), "r"(a1), "r"(a2), "r"(a3), "r"(b0), "r"(b1));
}
__device__ __forceinline__ void cp16(void* sdst, const void* gsrc) {
    uint32_t s = (uint32_t)__cvta_generic_to_shared(sdst);
    asm volatile("cp.async.cg.shared.global [%0], [%1], 16;\n" :: "r"(s), "l"(gsrc));
}
__device__ __forceinline__ uint32_t sm32(const void* p) {
    return (uint32_t)__cvta_generic_to_shared(p);
}
__device__ __forceinline__ void ldsm_x4(uint32_t& r0, uint32_t& r1,
                                        uint32_t& r2, uint32_t& r3, uint32_t addr) {
    asm volatile("ldmatrix.sync.aligned.m8n8.x4.shared.b16 {%0,%1,%2,%3}, [%4];"
        : "=r"(r0), "=r"(r1), "=r"(r2), "=r"(r3) : "r"(addr));
}
__device__ __forceinline__ void mbar_init(uint32_t a, uint32_t cnt) {
    asm volatile("mbarrier.init.shared.b64 [%0], %1;" :: "r"(a), "r"(cnt) : "memory");
}
__device__ __forceinline__ void mbar_expect(uint32_t a, uint32_t bytes) {
    asm volatile("mbarrier.arrive.expect_tx.shared.b64 _, [%0], %1;"
                 :: "r"(a), "r"(bytes) : "memory");
}
__device__ __forceinline__ void bulk_ld_mc(uint32_t sdst, const void* g,
                                           uint32_t bytes, uint32_t mbar,
                                           uint16_t mask) {
    asm volatile(
        "cp.async.bulk.shared::cluster.global.mbarrier::complete_tx::bytes"
        ".multicast::cluster [%0], [%1], %2, [%3], %4;"
        :: "r"(sdst), "l"(g), "r"(bytes), "r"(mbar), "h"(mask) : "memory");
}
__device__ __forceinline__ void mbar_wait(uint32_t a, uint32_t parity) {
    uint32_t done;
    asm volatile(
        "{\n.reg .pred p;\n"
        "mbarrier.try_wait.parity.acquire.cta.shared::cta.b64 p, [%1], %2;\n"
        "selp.b32 %0, 1, 0, p;\n}"
        : "=r"(done) : "r"(a), "r"(parity) : "memory");
    while (!done) {
        asm volatile(
            "{\n.reg .pred p;\n"
            "mbarrier.try_wait.parity.acquire.cta.shared::cta.b64 p, [%1], %2, 0x989680;\n"
            "selp.b32 %0, 1, 0, p;\n}"
            : "=r"(done) : "r"(a), "r"(parity) : "memory");
    }
}
__device__ __forceinline__ unsigned atom_acqrel(unsigned* p, unsigned v) {
    unsigned r;
    asm volatile("atom.add.acq_rel.gpu.global.u32 %0, [%1], %2;"
                 : "=r"(r) : "l"(p), "r"(v) : "memory");
    return r;
}
__device__ __forceinline__ unsigned ld_acquire(const unsigned* p) {
    unsigned r;
    asm volatile("ld.acquire.gpu.global.u32 %0, [%1];" : "=r"(r) : "l"(p) : "memory");
    return r;
}
__device__ __forceinline__ float fsig(float x) {
    return __fdividef(1.f, 1.f + __expf(-x));
}
__device__ __forceinline__ float ftanh(float x) {
    return __fdividef(2.f, 1.f + __expf(-2.f*x)) - 1.f;
}

// ---- embedding + char CNN (vectorized; also resets barrier state) ---------
__global__ void k_embed(const int* __restrict__ sent, const int* __restrict__ chars,
                        const float* __restrict__ wemb, const float* __restrict__ cemb,
                        const float* __restrict__ convw, const float* __restrict__ convb) {
    __shared__ float4 ce4[LCv*65];
    __shared__ float4 cw4[LCHv*193];
    __shared__ float  phi[WNv*LCHv];
    const int bp = blockIdx.x;
    const int tid = threadIdx.x;

    if (bp == 0 && tid < 4*32) g_chk[tid] = 0u;   // reset chunk counters

    for (int u = tid; u < LCv*64; u += 128) {
        int l = u >> 6, e4 = u & 63;
        int ci = chars[bp*LCv + l];
        ce4[l*65 + e4] = ((const float4*)cemb)[(size_t)ci*64 + e4];
    }
    for (int u = tid; u < LCHv*192; u += 128) {
        int c = u / 192, r = u - c*192;
        cw4[c*193 + r] = ((const float4*)convw)[(size_t)c*192 + r];
    }
    __syncthreads();

    int wi = sent[bp];
    for (int e4 = tid; e4 < 64; e4 += 128)
        *(float4*)&g_X[(size_t)bp*Dv + e4*4] = ((const float4*)wemb)[(size_t)wi*64 + e4];

    if (tid < WNv*LCHv) {
        int w = tid >> 2, c = tid & 3;
        float s0 = 0.f, s1 = 0.f, s2 = 0.f, s3 = 0.f;
        #pragma unroll
        for (int k = 0; k < Kw; k++) {
            const float4* cc = ce4 + (w + k)*65;
            const float4* cw = cw4 + c*193 + k*64;
            #pragma unroll
            for (int e = 0; e < 64; e += 4) {
                float4 a0 = cc[e],   b0 = cw[e];
                float4 a1 = cc[e+1], b1 = cw[e+1];
                float4 a2 = cc[e+2], b2 = cw[e+2];
                float4 a3 = cc[e+3], b3 = cw[e+3];
                s0 += a0.x*b0.x + a0.y*b0.y + a0.z*b0.z + a0.w*b0.w;
                s1 += a1.x*b1.x + a1.y*b1.y + a1.z*b1.z + a1.w*b1.w;
                s2 += a2.x*b2.x + a2.y*b2.y + a2.z*b2.z + a2.w*b2.w;
                s3 += a3.x*b3.x + a3.y*b3.y + a3.z*b3.z + a3.w*b3.w;
            }
        }
        phi[w*LCHv + c] = s0 + s1 + s2 + s3 + convb[c];
    }
    __syncthreads();
    if (tid < LCHv) {
        float m = -1e30f;
        #pragma unroll
        for (int w = 0; w < WNv; w++) m = fmaxf(m, phi[w*LCHv + tid]);
        g_X[(size_t)bp*Dv + Ev + tid] = m;
    }
}

// ---- input GEMM (tf32 MMA, 256 threads, W-tile reuse + double buffer) -----
__global__ void __launch_bounds__(256, 1) k_ingemm(const float* __restrict__ w_ih,
                                                   const float* __restrict__ b_ih,
                                                   const float* __restrict__ b_hh) {
    extern __shared__ uint32_t s[];
    uint32_t* Ws = s;
    uint32_t* Xb[2] = { s + 64*XS_STRIDE, s + 2*64*XS_STRIDE };
    const int j0 = blockIdx.x * 64;
    const int tid = threadIdx.x, warp = tid >> 5, lane = tid & 31;
    const int gid = lane >> 2, tig = lane & 3;
    const int m0 = (warp & 3) * 16, n0 = (warp >> 2) * 32;

    for (int r = tid; r < 64; r += 256) {
        #pragma unroll
        for (int c = 260; c < 268; c++) {
            Ws[r*XS_STRIDE + c] = 0u;
            Xb[0][r*XS_STRIDE + c] = 0u;
            Xb[1][r*XS_STRIDE + c] = 0u;
        }
    }
    for (int u = tid; u < 64*65; u += 256) {
        int r = u / 65, c = u - r*65;
        cp16(&Ws[r*XS_STRIDE + c*4], &w_ih[(size_t)(j0 + r)*Dv + c*4]);
    }
    {
        int i0 = (blockIdx.y*5 + 0) * 64;
        for (int u = tid; u < 64*65; u += 256) {
            int r = u / 65, c = u - r*65;
            cp16(&Xb[0][r*XS_STRIDE + c*4], &g_X[(size_t)(i0 + r)*Dv + c*4]);
        }
    }
    asm volatile("cp.async.commit_group;\n");

    for (int rt = 0; rt < 5; rt++) {
        const int i0 = (blockIdx.y*5 + rt) * 64;
        uint32_t* Xs = Xb[rt & 1];
        asm volatile("cp.async.wait_group 0;\n");
        __syncthreads();
        if (rt < 4) {
            int i1 = (blockIdx.y*5 + rt + 1) * 64;
            uint32_t* Xn = Xb[(rt+1) & 1];
            for (int u = tid; u < 64*65; u += 256) {
                int r = u / 65, c = u - r*65;
                cp16(&Xn[r*XS_STRIDE + c*4], &g_X[(size_t)(i1 + r)*Dv + c*4]);
            }
            asm volatile("cp.async.commit_group;\n");
        }

        float d[4][4] = {};
        #pragma unroll 1
        for (int kc = 0; kc < 33; kc++) {
            int kb = kc*8;
            int ar = (m0 + gid)*XS_STRIDE + kb;
            uint32_t a0 = Xs[ar + tig];
            uint32_t a1 = Xs[ar + 8*XS_STRIDE + tig];
            uint32_t a2 = Xs[ar + tig + 4];
            uint32_t a3 = Xs[ar + 8*XS_STRIDE + tig + 4];
            #pragma unroll
            for (int ns = 0; ns < 4; ns++) {
                uint32_t b0 = Ws[(n0 + ns*8 + gid)*XS_STRIDE + kb + tig];
                uint32_t b1 = Ws[(n0 + ns*8 + gid)*XS_STRIDE + kb + tig + 4];
                mma_tf32(d[ns], a0, a1, a2, a3, b0, b1);
            }
        }

        #pragma unroll
        for (int ns = 0; ns < 4; ns++) {
            int row = i0 + m0 + gid;
            int col = j0 + n0 + ns*8 + tig*2;
            float bb0 = b_ih[col] + b_hh[col];
            float bb1 = b_ih[col+1] + b_hh[col+1];
            *(float2*)&g_Gin[(size_t)row*G4 + col] =
                make_float2(d[ns][0] + bb0, d[ns][1] + bb1);
            *(float2*)&g_Gin[(size_t)(row+8)*G4 + col] =
                make_float2(d[ns][2] + bb0, d[ns][3] + bb1);
        }
        __syncthreads();
    }
}

// ---- persistent tensor-core LSTM (chunked barrier + TMA multicast) --------
__global__ void __launch_bounds__(NT, 1) __cluster_dims__(2, 1, 1)
k_lstm(const float* __restrict__ w_hh) {
    extern __shared__ uint32_t smw[];
    uint32_t* Aw  = smw;                               // h_prev bf16 [64][1032]
    uint32_t* Ww  = smw + 64*AW_STRIDE;                // W bf16 [32][1032]
    float*    Red = (float*)(smw + 64*AW_STRIDE + 32*WW_STRIDE); // [4][32][9]
    uint32_t  mbarBase = sm32(Red + 4*32*9);           // 4 mbarriers (8B each)

    const int tid  = threadIdx.x;
    const int warp = tid >> 5, lane = tid & 31;
    const int gid  = lane >> 2, tig = lane & 3;
    const int bx   = blockIdx.x;
    const int j0   = bx * 8;
    const int mt   = warp & 3, m0 = mt*16;
    const int nh   = warp >> 2;
    const uint32_t aw32 = sm32(Aw);
    uint32_t rank; asm("mov.u32 %0, %%cluster_ctarank;" : "=r"(rank));

    if (tid == 0) {
        #pragma unroll
        for (int c = 0; c < 4; c++) mbar_init(mbarBase + c*8, 1u);
    }

    // load + convert W slice to bf16 once
    {
        __nv_bfloat16* Whh = (__nv_bfloat16*)Ww;
        for (int u = tid; u < 32*Hv; u += NT) {
            int n = u >> 10, k = u & (Hv-1);
            int gate = n >> 3, jj = n & 7;
            Whh[n*(2*WW_STRIDE) + k] =
                __float2bfloat16(w_hh[(size_t)(gate*Hv + j0 + jj)*Hv + k]);
        }
    }
    __syncthreads();
    // peer mbar-init visibility: peer's first multicast TMA is only issued
    // after polling chunk counters of step 0, which follow this CTA's stores.

    // per-lane ldmatrix base addresses
    const int sel = lane >> 3, lr = lane & 7;
    const int rowA  = m0 + lr + ((sel & 1) ? 8 : 0);
    const int wordA = (sel >= 2) ? 4 : 0;
    const uint32_t aBase = sm32(Aw + rowA*AW_STRIDE + wordA);
    const int rowW  = (nh*2 + (sel >> 1))*8 + lr;
    const int wordW = (sel & 1) ? 4 : 0;
    const uint32_t wBase = sm32(Ww + rowW*WW_STRIDE + wordW);

    float creg[4] = {0.f, 0.f, 0.f, 0.f};

    float2 gin[4];
    #pragma unroll
    for (int g2 = 0; g2 < 2; g2++)
        #pragma unroll
        for (int r = 0; r < 2; r++)
            gin[g2*2+r] = *(const float2*)
                &g_Gin[(size_t)(m0 + gid + r*8)*G4 + (nh*2+g2)*Hv + j0 + tig*2];

    for (int t = 0; t < Pv; t++) {
        float d[8];
        #pragma unroll
        for (int i = 0; i < 8; i++) d[i] = 0.f;

        if (t > 0) {
            // warp mt waits only for its own 16-row chunk
            mbar_wait(mbarBase + mt*8, (uint32_t)((t-1) & 1));

            #pragma unroll 4
            for (int kc = 0; kc < 64; kc++) {
                uint32_t a0, a1, a2, a3, w0, w1, w2, w3;
                ldsm_x4(a0, a1, a2, a3, aBase + kc*32);
                ldsm_x4(w0, w1, w2, w3, wBase + kc*32);
                mma_bf16(d + 0, a0, a1, a2, a3, w0, w1);
                mma_bf16(d + 4, a0, a1, a2, a3, w2, w3);
            }
        }

        if (nh == 0) {
            float* rw = Red + (mt*32 + lane)*9;
            rw[0] = d[0] + gin[0].x; rw[1] = d[1] + gin[0].y;
            rw[2] = d[2] + gin[1].x; rw[3] = d[3] + gin[1].y;
            rw[4] = d[4] + gin[2].x; rw[5] = d[5] + gin[2].y;
            rw[6] = d[6] + gin[3].x; rw[7] = d[7] + gin[3].y;
        }
        __syncthreads();

        if (nh == 1) {
            const float* rr = Red + (mt*32 + lane)*9;
            __nv_bfloat16* hdst = g_HSb + (size_t)t*Bv*HS_STRIDE;
            float hv[4];
            #pragma unroll
            for (int idx = 0; idx < 4; idx++) {
                int r = idx >> 1, p = idx & 1;
                float iv = rr[idx];
                float fv = rr[4 + idx];
                float gv = d[idx]     + ((p==0) ? gin[r].x   : gin[r].y);
                float ov = d[4 + idx] + ((p==0) ? gin[2+r].x : gin[2+r].y);
                float is = fsig(iv);
                float fs = fsig(fv);
                float gs = ftanh(gv);
                float os = fsig(ov);
                float cc = fs*creg[idx] + is*gs;
                creg[idx] = cc;
                hv[idx] = os*ftanh(cc);
            }
            __nv_bfloat162 h01, h23;
            h01.x = __float2bfloat16(hv[0]); h01.y = __float2bfloat16(hv[1]);
            h23.x = __float2bfloat16(hv[2]); h23.y = __float2bfloat16(hv[3]);
            *(__nv_bfloat162*)&hdst[(size_t)(m0 + gid)*HS_STRIDE + j0 + tig*2]     = h01;
            *(__nv_bfloat162*)&hdst[(size_t)(m0 + gid + 8)*HS_STRIDE + j0 + tig*2] = h23;
        }

        // chunked grid barrier: per-chunk monotonic counters; TMA per chunk
        if (t < Pv - 1) {
            asm volatile("fence.proxy.async;" ::: "memory");
            __syncthreads();   // CTA-wide HB: all h stores precede arrivals
            if (nh == 1 && lane == 0)
                atom_acqrel(&g_chk[mt*32], 1u);       // release chunk mt
            // overlap: prefetch gin for t+1
            #pragma unroll
            for (int g2 = 0; g2 < 2; g2++)
                #pragma unroll
                for (int r = 0; r < 2; r++)
                    gin[g2*2+r] = *(const float2*)
                        &g_Gin[(size_t)((t+1)*Bv + m0 + gid + r*8)*G4 + (nh*2+g2)*Hv + j0 + tig*2];
            if (tid == 0) {
                // local expects for all 4 chunks (signed tx tolerates races)
                #pragma unroll
                for (int c = 0; c < 4; c++)
                    mbar_expect(mbarBase + c*8, HCHUNK_BYTES);
                const char* src = (const char*)g_HSb
                    + (size_t)t * (size_t)(Bv*HROW_BYTES);
                const unsigned target = (unsigned)(NB*(t + 1));
                #pragma unroll
                for (int q = 0; q < 2; q++) {
                    int c = (int)rank*2 + q;
                    while (ld_acquire(&g_chk[c*32]) < target) { }
                    bulk_ld_mc(aw32 + c*HCHUNK_BYTES,
                               src + (size_t)c*HCHUNK_BYTES,
                               HCHUNK_BYTES, mbarBase + c*8, (uint16_t)3u);
                }
            }
            __syncthreads();
        }
    }

    // cluster-safe exit
    asm volatile("barrier.cluster.arrive.aligned;" ::: "memory");
    asm volatile("barrier.cluster.wait.aligned;" ::: "memory");
}

// ---- head GEMM (tf32 MMA, 256 threads; padded-HS reads) -------------------
__global__ void __launch_bounds__(256, 1) k_tag(const float* __restrict__ out_w,
                                                const float* __restrict__ out_b) {
    extern __shared__ uint32_t s[];
    uint32_t* As = s;                       // [64][140]
    uint32_t* Bs = s + 64*TG_STRIDE;        // [64][140]
    const int i0 = blockIdx.x * 64;
    const int tid = threadIdx.x, warp = tid >> 5, lane = tid & 31;
    const int gid = lane >> 2, tig = lane & 3;
    const int m0 = (warp & 3) * 16, n0 = (warp >> 2) * 32;

    float d[4][4] = {};
    for (int kc8 = 0; kc8 < 8; kc8++) {
        int kb = kc8 * 128;
        __syncthreads();
        for (int u = tid; u < 64*16; u += 256) {
            int r = u >> 4, c = u & 15;
            uint4 v = *(const uint4*)(g_HSb + (size_t)(i0 + r)*HS_STRIDE + kb + c*8);
            const uint32_t* pv = (const uint32_t*)&v;
            uint32_t* dst = &As[r*TG_STRIDE + c*8];
            #pragma unroll
            for (int j = 0; j < 4; j++) {
                dst[j*2]     = pv[j] << 16;
                dst[j*2 + 1] = pv[j] & 0xFFFF0000u;
            }
        }
        for (int u = tid; u < 64*32; u += 256) {
            int r = u >> 5, c = u & 31;
            float4 v = (r < TAGSv)
                ? *(const float4*)&out_w[(size_t)r*Hv + kb + c*4]
                : make_float4(0.f,0.f,0.f,0.f);
            uint4 tv = { f2tf32(v.x), f2tf32(v.y), f2tf32(v.z), f2tf32(v.w) };
            *(uint4*)&Bs[r*TG_STRIDE + c*4] = tv;
        }
        __syncthreads();

        #pragma unroll
        for (int kk = 0; kk < 16; kk++) {
            int kw = kk*8;
            int ar = (m0 + gid)*TG_STRIDE + kw;
            uint32_t a0 = As[ar + tig];
            uint32_t a1 = As[ar + 8*TG_STRIDE + tig];
            uint32_t a2 = As[ar + tig + 4];
            uint32_t a3 = As[ar + 8*TG_STRIDE + tig + 4];
            #pragma unroll
            for (int ns = 0; ns < 4; ns++) {
                uint32_t b0 = Bs[(n0 + ns*8 + gid)*TG_STRIDE + kw + tig];
                uint32_t b1 = Bs[(n0 + ns*8 + gid)*TG_STRIDE + kw + tig + 4];
                mma_tf32(d[ns], a0, a1, a2, a3, b0, b1);
            }
        }
    }

    #pragma unroll
    for (int ns = 0; ns < 4; ns++) {
        int row = i0 + m0 + gid;
        int col = n0 + ns*8 + tig*2;
        if (col < TAGSv) {
            float b0 = out_b[col];
            float b1 = (col+1 < TAGSv) ? out_b[col+1] : 0.f;
            g_TS[row*TAGSv + col] = d[ns][0] + b0;
            if (col+1 < TAGSv) g_TS[row*TAGSv + col+1] = d[ns][1] + b1;
            g_TS[(row+8)*TAGSv + col] = d[ns][2] + b0;
            if (col+1 < TAGSv) g_TS[(row+8)*TAGSv + col+1] = d[ns][3] + b1;
        }
    }
}

// ---- log_softmax over P (smem-staged, coalesced) --------------------------
__global__ void k_lsm(float* __restrict__ out) {
    __shared__ float ts[Pv*TAGSv];
    __shared__ float lse[TAGSv];
    int b = blockIdx.x;
    int tid = threadIdx.x;
    for (int u = tid; u < Pv*TAGSv; u += 256)
        ts[u] = g_TS[b*Pv*TAGSv + u];
    __syncthreads();
    if (tid < TAGSv) {
        float mx = -1e30f;
        for (int p = 0; p < Pv; p++) mx = fmaxf(mx, ts[p*TAGSv + tid]);
        float sacc = 0.f;
        for (int p = 0; p < Pv; p++) sacc += expf(ts[p*TAGSv + tid] - mx);
        lse[tid] = mx + logf(sacc);
    }
    __syncthreads();
    for (int u = tid; u < Pv*TAGSv; u += 256) {
        int tg = u - (u/TAGSv)*TAGSv;
        out[(size_t)b*Pv*TAGSv + u] = ts[u] - lse[tg];
    }
}

// ---------------------------------------------------------------------------
extern "C" void kernel_launch(void* const* d_in, const int* in_sizes, int n_in,
                              void* d_out, int out_size) {
    const int*   sent  = (const int*)  d_in[0];
    const int*   chars = (const int*)  d_in[1];
    const float* wemb  = (const float*)d_in[2];
    const float* cemb  = (const float*)d_in[3];
    const float* convw = (const float*)d_in[4];
    const float* convb = (const float*)d_in[5];
    const float* w_ih  = (const float*)d_in[6];
    const float* w_hh  = (const float*)d_in[7];
    const float* b_ih  = (const float*)d_in[8];
    const float* b_hh  = (const float*)d_in[9];
    const float* out_w = (const float*)d_in[10];
    const float* out_b = (const float*)d_in[11];
    float* out = (float*)d_out;

    const int SMEM_L  = (64*AW_STRIDE + 32*WW_STRIDE)*4 + 4*32*9*4 + 64;
    const int SMEM_IN = 3*64*XS_STRIDE*4;
    const int SMEM_TG = 2*64*TG_STRIDE*4;
    static int smem_set = 0;
    if (!smem_set) {
        cudaFuncSetAttribute(k_lstm,   cudaFuncAttributeMaxDynamicSharedMemorySize, SMEM_L);
        cudaFuncSetAttribute(k_ingemm, cudaFuncAttributeMaxDynamicSharedMemorySize, SMEM_IN);
        cudaFuncSetAttribute(k_tag,    cudaFuncAttributeMaxDynamicSharedMemorySize, SMEM_TG);
        smem_set = 1;
    }

    k_embed<<<ROWS, 128>>>(sent, chars, wemb, cemb, convw, convb);
    dim3 g2(G4/64, 16);
    k_ingemm<<<g2, 256, SMEM_IN>>>(w_ih, b_ih, b_hh);
    k_lstm<<<NB, NT, SMEM_L>>>(w_hh);
    k_tag<<<ROWS/64, 256, SMEM_TG>>>(out_w, out_b);
    k_lsm<<<Bv, 256>>>(out);
}